// round 1
// baseline (speedup 1.0000x reference)
#include <cuda_runtime.h>
#include <math.h>
#include <stdint.h>

#define B_   4
#define T_   2048
#define HID_ 2048
#define NH_  16
#define HD_  128

// ---------------- scratch (static __device__ — no allocations allowed) -----
__device__ float g_qkv[(size_t)B_ * T_ * 3 * HID_];     // [B,T,3,NH,HD]
__device__ float g_q[(size_t)B_ * NH_ * T_ * HD_];      // [B,NH,T,HD] (roped, pre-scaled? no: raw roped)
__device__ float g_k[(size_t)B_ * NH_ * T_ * HD_];
__device__ float g_v[(size_t)B_ * NH_ * T_ * HD_];
__device__ float g_attn[(size_t)B_ * T_ * HID_];        // [B,T,HID]

// ---------------- SGEMM (NT): C[M,N] = A[M,K] @ B[N,K]^T (+bias) -----------
// BM=BN=128, BK=16, 256 threads, 8x8 per-thread tile.
__global__ void __launch_bounds__(256)
sgemm_nt_kernel(const float* __restrict__ A, const float* __restrict__ Bm,
                const float* __restrict__ bias, float* __restrict__ C,
                int M, int N, int K)
{
    const int bx = blockIdx.x;          // N tile
    const int by = blockIdx.y;          // M tile
    const int tid = threadIdx.x;
    const int tx = tid & 15, ty = tid >> 4;

    __shared__ __align__(16) float As[16][132];   // [k][m], padded
    __shared__ __align__(16) float Bs[16][132];   // [k][n], padded

    const float* Ab = A + (size_t)by * 128 * K;
    const float* Bb = Bm + (size_t)bx * 128 * K;

    float acc[8][8];
#pragma unroll
    for (int i = 0; i < 8; ++i)
#pragma unroll
        for (int j = 0; j < 8; ++j) acc[i][j] = 0.f;

    const int lrow = tid >> 2;            // 0..63
    const int lq   = (tid & 3) * 4;       // 0,4,8,12

    for (int kt = 0; kt < K; kt += 16) {
        float4 a0 = *(const float4*)(Ab + (size_t)lrow        * K + kt + lq);
        float4 a1 = *(const float4*)(Ab + (size_t)(lrow + 64) * K + kt + lq);
        float4 b0 = *(const float4*)(Bb + (size_t)lrow        * K + kt + lq);
        float4 b1 = *(const float4*)(Bb + (size_t)(lrow + 64) * K + kt + lq);
        __syncthreads();
        As[lq+0][lrow]    = a0.x; As[lq+1][lrow]    = a0.y;
        As[lq+2][lrow]    = a0.z; As[lq+3][lrow]    = a0.w;
        As[lq+0][lrow+64] = a1.x; As[lq+1][lrow+64] = a1.y;
        As[lq+2][lrow+64] = a1.z; As[lq+3][lrow+64] = a1.w;
        Bs[lq+0][lrow]    = b0.x; Bs[lq+1][lrow]    = b0.y;
        Bs[lq+2][lrow]    = b0.z; Bs[lq+3][lrow]    = b0.w;
        Bs[lq+0][lrow+64] = b1.x; Bs[lq+1][lrow+64] = b1.y;
        Bs[lq+2][lrow+64] = b1.z; Bs[lq+3][lrow+64] = b1.w;
        __syncthreads();

#pragma unroll
        for (int kk = 0; kk < 16; ++kk) {
            float a[8], b[8];
            *(float4*)&a[0] = *(const float4*)&As[kk][ty*8];
            *(float4*)&a[4] = *(const float4*)&As[kk][ty*8 + 4];
            *(float4*)&b[0] = *(const float4*)&Bs[kk][tx*8];
            *(float4*)&b[4] = *(const float4*)&Bs[kk][tx*8 + 4];
#pragma unroll
            for (int i = 0; i < 8; ++i)
#pragma unroll
                for (int j = 0; j < 8; ++j)
                    acc[i][j] += a[i] * b[j];
        }
    }

    float bv[8];
#pragma unroll
    for (int j = 0; j < 8; ++j) bv[j] = 0.f;
    if (bias) {
        *(float4*)&bv[0] = *(const float4*)(bias + bx*128 + tx*8);
        *(float4*)&bv[4] = *(const float4*)(bias + bx*128 + tx*8 + 4);
    }
#pragma unroll
    for (int i = 0; i < 8; ++i) {
        float* Cp = C + (size_t)(by*128 + ty*8 + i) * N + bx*128 + tx*8;
        float4 c0 = make_float4(acc[i][0]+bv[0], acc[i][1]+bv[1], acc[i][2]+bv[2], acc[i][3]+bv[3]);
        float4 c1 = make_float4(acc[i][4]+bv[4], acc[i][5]+bv[5], acc[i][6]+bv[6], acc[i][7]+bv[7]);
        *(float4*)Cp       = c0;
        *(float4*)(Cp + 4) = c1;
    }
}

// ---------------- RoPE + split + [B,T,3,NH,HD] -> [B,NH,T,HD] ---------------
__global__ void __launch_bounds__(256)
rope_split_kernel(const float* __restrict__ qkv,
                  const float* __restrict__ cosb, const float* __restrict__ sinb,
                  float* __restrict__ Q, float* __restrict__ K, float* __restrict__ V)
{
    size_t idx = (size_t)blockIdx.x * blockDim.x + threadIdx.x;
    int d2 = (int)(idx & 63);
    size_t r = idx >> 6;
    int nh = (int)(r & (NH_ - 1)); r >>= 4;
    int t  = (int)(r & (T_ - 1));
    int b  = (int)(r >> 11);

    const float* base = qkv + ((size_t)(b * T_ + t)) * 3 * HID_ + nh * HD_ + 2 * d2;
    float2 qp = *(const float2*)(base);
    float2 kp = *(const float2*)(base + HID_);
    float2 vp = *(const float2*)(base + 2 * HID_);
    float c = cosb[t * 64 + d2];
    float s = sinb[t * 64 + d2];

    size_t o = (((size_t)(b * NH_ + nh)) * T_ + t) * HD_ + 2 * d2;
    *(float2*)(Q + o) = make_float2(qp.x * c - qp.y * s, qp.x * s + qp.y * c);
    *(float2*)(K + o) = make_float2(kp.x * c - kp.y * s, kp.x * s + kp.y * c);
    *(float2*)(V + o) = vp;
}

// ---------------- Flash attention (fp32, online softmax) -------------------
// BM=BN=64, HD=128, 256 threads. Q/K stored transposed in smem ([k][row]) so
// the S-phase inner loop is 2x LDS.128 + 16 FFMA per k. P stored transposed
// ([kv][row]) so the PV phase is 3x LDS.128 + 32 FFMA per kv.
#define ATP 68   // padded row stride for Pst

__global__ void __launch_bounds__(256)
flash_attn_kernel(const float* __restrict__ Q, const float* __restrict__ K,
                  const float* __restrict__ V, float* __restrict__ O)
{
    const int qt = blockIdx.x, h = blockIdx.y, b = blockIdx.z;
    const int tid = threadIdx.x;
    const int ty = tid >> 4, tx = tid & 15;

    extern __shared__ __align__(16) float sm[];
    float* Qst = sm;                  // [128][64]
    float* Kst = Qst + 128 * 64;      // [128][64]
    float* Vs  = Kst + 128 * 64;      // [64][128]
    float* Pst = Vs  + 64 * 128;      // [64][ATP]

    const float scale = 0.088388347648318447f;  // 1/sqrt(128)
    const float* Qg = Q + (((size_t)b * NH_ + h) * T_ + (size_t)qt * 64) * HD_;
    const float* Kg = K + (((size_t)b * NH_ + h) * T_) * HD_;
    const float* Vg = V + (((size_t)b * NH_ + h) * T_) * HD_;

    // Q tile: load, scale, transpose into smem
    for (int i = tid; i < 64 * 32; i += 256) {
        int row = i >> 5, c4 = (i & 31) << 2;
        float4 qv = *(const float4*)(Qg + (size_t)row * HD_ + c4);
        Qst[(c4+0)*64 + row] = qv.x * scale;
        Qst[(c4+1)*64 + row] = qv.y * scale;
        Qst[(c4+2)*64 + row] = qv.z * scale;
        Qst[(c4+3)*64 + row] = qv.w * scale;
    }

    float acc[4][8];
#pragma unroll
    for (int i = 0; i < 4; ++i)
#pragma unroll
        for (int j = 0; j < 8; ++j) acc[i][j] = 0.f;
    float m_i[4], l_i[4];
#pragma unroll
    for (int i = 0; i < 4; ++i) { m_i[i] = -1e30f; l_i[i] = 0.f; }

    for (int jt = 0; jt < T_ / 64; ++jt) {
        __syncthreads();   // prior PV phase done with Vs/Pst
        const float* Kgj = Kg + (size_t)jt * 64 * HD_;
        const float* Vgj = Vg + (size_t)jt * 64 * HD_;
        for (int i = tid; i < 64 * 32; i += 256) {
            int row = i >> 5, c4 = (i & 31) << 2;
            float4 kv = *(const float4*)(Kgj + (size_t)row * HD_ + c4);
            Kst[(c4+0)*64 + row] = kv.x;
            Kst[(c4+1)*64 + row] = kv.y;
            Kst[(c4+2)*64 + row] = kv.z;
            Kst[(c4+3)*64 + row] = kv.w;
            *(float4*)(Vs + row * HD_ + c4) = *(const float4*)(Vgj + (size_t)row * HD_ + c4);
        }
        __syncthreads();

        // ---- S = Q K^T (4x4 per thread) ----
        float s[4][4];
#pragma unroll
        for (int i = 0; i < 4; ++i)
#pragma unroll
            for (int j = 0; j < 4; ++j) s[i][j] = 0.f;

#pragma unroll 8
        for (int k = 0; k < HD_; ++k) {
            float4 qv = *(const float4*)(Qst + k * 64 + ty * 4);
            float4 kv = *(const float4*)(Kst + k * 64 + tx * 4);
            float qa[4] = {qv.x, qv.y, qv.z, qv.w};
            float ka[4] = {kv.x, kv.y, kv.z, kv.w};
#pragma unroll
            for (int i = 0; i < 4; ++i)
#pragma unroll
                for (int j = 0; j < 4; ++j)
                    s[i][j] += qa[i] * ka[j];
        }

        // ---- online softmax per row (rows = ty*4+i, shared by 16 tx lanes) ----
#pragma unroll
        for (int i = 0; i < 4; ++i) {
            float mx = fmaxf(fmaxf(s[i][0], s[i][1]), fmaxf(s[i][2], s[i][3]));
#pragma unroll
            for (int off = 8; off > 0; off >>= 1)
                mx = fmaxf(mx, __shfl_xor_sync(0xffffffffu, mx, off, 16));
            float m_new = fmaxf(m_i[i], mx);
            float corr = __expf(m_i[i] - m_new);
            m_i[i] = m_new;
            float rs = 0.f;
#pragma unroll
            for (int j = 0; j < 4; ++j) {
                float p = __expf(s[i][j] - m_new);
                s[i][j] = p;
                rs += p;
            }
#pragma unroll
            for (int off = 8; off > 0; off >>= 1)
                rs += __shfl_xor_sync(0xffffffffu, rs, off, 16);
            l_i[i] = l_i[i] * corr + rs;
#pragma unroll
            for (int j = 0; j < 8; ++j) acc[i][j] *= corr;
        }

        // ---- write P transposed: Pst[kv][row] ----
#pragma unroll
        for (int j = 0; j < 4; ++j) {
            float4 pv = make_float4(s[0][j], s[1][j], s[2][j], s[3][j]);
            *(float4*)(Pst + (tx * 4 + j) * ATP + ty * 4) = pv;
        }
        __syncthreads();

        // ---- O += P @ V (4 rows x 8 cols per thread) ----
#pragma unroll 4
        for (int kv = 0; kv < 64; ++kv) {
            float4 p  = *(const float4*)(Pst + kv * ATP + ty * 4);
            float4 v0 = *(const float4*)(Vs + kv * HD_ + tx * 8);
            float4 v1 = *(const float4*)(Vs + kv * HD_ + tx * 8 + 4);
            float pa[4] = {p.x, p.y, p.z, p.w};
            float va[8] = {v0.x, v0.y, v0.z, v0.w, v1.x, v1.y, v1.z, v1.w};
#pragma unroll
            for (int i = 0; i < 4; ++i)
#pragma unroll
                for (int j = 0; j < 8; ++j)
                    acc[i][j] += pa[i] * va[j];
        }
    }

    // ---- epilogue: normalize, write [B,T,HID] ----
#pragma unroll
    for (int i = 0; i < 4; ++i) {
        float inv = 1.f / l_i[i];
        int t = qt * 64 + ty * 4 + i;
        float* Op = O + ((size_t)b * T_ + t) * HID_ + h * HD_ + tx * 8;
        float4 o0 = make_float4(acc[i][0]*inv, acc[i][1]*inv, acc[i][2]*inv, acc[i][3]*inv);
        float4 o1 = make_float4(acc[i][4]*inv, acc[i][5]*inv, acc[i][6]*inv, acc[i][7]*inv);
        *(float4*)Op       = o0;
        *(float4*)(Op + 4) = o1;
    }
}

// ---------------- launch ----------------------------------------------------
extern "C" void kernel_launch(void* const* d_in, const int* in_sizes, int n_in,
                              void* d_out, int out_size)
{
    const float* x      = (const float*)d_in[0];
    const float* w_qkv  = (const float*)d_in[1];
    const float* w_proj = (const float*)d_in[2];
    const float* b_proj = (const float*)d_in[3];
    const float* cosb   = (const float*)d_in[4];
    const float* sinb   = (const float*)d_in[5];
    float* out = (float*)d_out;

    float *qkv, *q, *k, *v, *attn;
    cudaGetSymbolAddress((void**)&qkv,  g_qkv);
    cudaGetSymbolAddress((void**)&q,    g_q);
    cudaGetSymbolAddress((void**)&k,    g_k);
    cudaGetSymbolAddress((void**)&v,    g_v);
    cudaGetSymbolAddress((void**)&attn, g_attn);

    const int SMEM_ATT = (128*64 + 128*64 + 64*128 + 64*ATP) * sizeof(float); // 115712
    cudaFuncSetAttribute(flash_attn_kernel,
                         cudaFuncAttributeMaxDynamicSharedMemorySize, SMEM_ATT);

    const int M = B_ * T_;          // 8192

    // 1) QKV projection: [8192,2048] @ [6144,2048]^T -> [8192,6144]
    dim3 g1(3 * HID_ / 128, M / 128);
    sgemm_nt_kernel<<<g1, 256>>>(x, w_qkv, nullptr, qkv, M, 3 * HID_, HID_);

    // 2) RoPE + split + head transpose
    size_t total = (size_t)B_ * T_ * NH_ * 64;
    rope_split_kernel<<<(unsigned)(total / 256), 256>>>(qkv, cosb, sinb, q, k, v);

    // 3) Flash attention
    dim3 ga(T_ / 64, NH_, B_);
    flash_attn_kernel<<<ga, 256, SMEM_ATT>>>(q, k, v, attn);

    // 4) Output projection + bias: [8192,2048] @ [2048,2048]^T + b -> out
    dim3 g2(HID_ / 128, M / 128);
    sgemm_nt_kernel<<<g2, 256>>>(attn, w_proj, b_proj, out, M, HID_, HID_);
}

// round 2
// speedup vs baseline: 6.9401x; 6.9401x over previous
#include <cuda_runtime.h>
#include <math.h>
#include <stdint.h>

#define B_   4
#define T_   2048
#define HID_ 2048
#define NH_  16
#define HD_  128

// ---------------- scratch ---------------------------------------------------
__device__ __align__(128) float g_qkv [(size_t)B_ * T_ * 3 * HID_];   // [B,T,3,HID]
__device__ __align__(128) float g_q   [(size_t)B_ * NH_ * T_ * HD_];  // [B,NH,T,HD] tf32, pre-scaled
__device__ __align__(128) float g_k   [(size_t)B_ * NH_ * T_ * HD_];  // [B,NH,T,HD] tf32
__device__ __align__(128) float g_v   [(size_t)B_ * NH_ * T_ * HD_];  // [B,NH,HD,T] tf32 (TRANSPOSED)
__device__ __align__(128) float g_attn[(size_t)B_ * T_ * HID_];       // [B,T,HID]

// ---------------- PTX helpers ----------------------------------------------
__device__ __forceinline__ uint32_t smem_u32(const void* p) {
    return (uint32_t)__cvta_generic_to_shared(p);
}
__device__ __forceinline__ void cp16(uint32_t s, const void* g) {
    asm volatile("cp.async.cg.shared.global [%0],[%1],16;\n" :: "r"(s), "l"(g));
}
__device__ __forceinline__ void cp_commit() { asm volatile("cp.async.commit_group;\n"); }
template<int N> __device__ __forceinline__ void cp_wait() {
    asm volatile("cp.async.wait_group %0;\n" :: "n"(N));
}
__device__ __forceinline__ void ldsm4(uint32_t* r, uint32_t a) {
    asm volatile("ldmatrix.sync.aligned.m8n8.x4.shared.b16 {%0,%1,%2,%3},[%4];\n"
                 : "=r"(r[0]), "=r"(r[1]), "=r"(r[2]), "=r"(r[3]) : "r"(a));
}
__device__ __forceinline__ void mma8(float* c, const uint32_t* a, uint32_t b0, uint32_t b1) {
    asm volatile("mma.sync.aligned.m16n8k8.row.col.f32.tf32.tf32.f32 "
                 "{%0,%1,%2,%3},{%4,%5,%6,%7},{%8,%9},{%0,%1,%2,%3};\n"
                 : "+f"(c[0]), "+f"(c[1]), "+f"(c[2]), "+f"(c[3])
                 : "r"(a[0]), "r"(a[1]), "r"(a[2]), "r"(a[3]), "r"(b0), "r"(b1));
}
__device__ __forceinline__ uint32_t f2tfu(float x) {
    uint32_t r; asm("cvt.rna.tf32.f32 %0,%1;\n" : "=r"(r) : "f"(x)); return r;
}
__device__ __forceinline__ float f2tf(float x) { return __uint_as_float(f2tfu(x)); }

// ---------------- tf32 GEMM (NT): C[M,N] = A[M,K] @ B[N,K]^T (+bias) --------
// 128x128x32 tiles, 8 warps (4M x 2N), warp tile 32x64, cp.async double buffer.
#define GS 36   // smem row stride (floats): 36 mod 32 = 4 -> ldmatrix conflict-free

__global__ void __launch_bounds__(256, 2)
gemm_tf32_nt(const float* __restrict__ A, const float* __restrict__ Bw,
             const float* __restrict__ bias, float* __restrict__ C,
             int M, int N, int K)
{
    extern __shared__ __align__(16) float gsm[];
    float* As = gsm;               // [2][128*GS]
    float* Bs = gsm + 2*128*GS;    // [2][128*GS]

    const int tid = threadIdx.x, l = tid & 31, w = tid >> 5;
    const int wm = w & 3, wn = w >> 2;
    const float* Ag = A  + (size_t)blockIdx.y * 128 * K;
    const float* Bg = Bw + (size_t)blockIdx.x * 128 * K;
    const int lr = tid >> 3, lc = (tid & 7) * 4;
    const uint32_t sA = smem_u32(As), sB = smem_u32(Bs);

    float acc[2][8][4];
#pragma unroll
    for (int i = 0; i < 2; ++i)
#pragma unroll
        for (int j = 0; j < 8; ++j)
#pragma unroll
            for (int k = 0; k < 4; ++k) acc[i][j][k] = 0.f;

    const int aOff = (wm*32 + (l & 7) + ((l >> 3) & 1) * 8) * GS + ((l >> 3) >> 1) * 4;
    const int bOff = (wn*64 + (l & 7) + ((l >> 4) & 1) * 8) * GS + ((l >> 3) & 1) * 4;

    // prefetch tile 0
#pragma unroll
    for (int p = 0; p < 4; ++p) {
        int r = lr + p * 32;
        cp16(sA + (r*GS + lc) * 4, Ag + (size_t)r * K + lc);
        cp16(sB + (r*GS + lc) * 4, Bg + (size_t)r * K + lc);
    }
    cp_commit();

    const int nkt = K >> 5;
    for (int kt = 0; kt < nkt; ++kt) {
        const int buf = kt & 1;
        cp_wait<0>();
        __syncthreads();
        if (kt + 1 < nkt) {
            const float* Ap = Ag + (size_t)(kt + 1) * 32;
            const float* Bp = Bg + (size_t)(kt + 1) * 32;
            const int o = (buf ^ 1) * 128 * GS;
#pragma unroll
            for (int p = 0; p < 4; ++p) {
                int r = lr + p * 32;
                cp16(sA + (o + r*GS + lc) * 4, Ap + (size_t)r * K + lc);
                cp16(sB + (o + r*GS + lc) * 4, Bp + (size_t)r * K + lc);
            }
            cp_commit();
        }
        const uint32_t aB = sA + buf * 128 * GS * 4;
        const uint32_t bB = sB + buf * 128 * GS * 4;
#pragma unroll
        for (int ks = 0; ks < 4; ++ks) {
            const int k8 = ks * 8;
            uint32_t a[2][4], bf[8][2];
#pragma unroll
            for (int mi = 0; mi < 2; ++mi) {
                ldsm4(a[mi], aB + (aOff + mi*16*GS + k8) * 4);
#pragma unroll
                for (int q = 0; q < 4; ++q) a[mi][q] = f2tfu(__uint_as_float(a[mi][q]));
            }
#pragma unroll
            for (int j = 0; j < 4; ++j) {
                uint32_t t[4];
                ldsm4(t, bB + (bOff + j*16*GS + k8) * 4);
                bf[2*j  ][0] = f2tfu(__uint_as_float(t[0]));
                bf[2*j  ][1] = f2tfu(__uint_as_float(t[1]));
                bf[2*j+1][0] = f2tfu(__uint_as_float(t[2]));
                bf[2*j+1][1] = f2tfu(__uint_as_float(t[3]));
            }
#pragma unroll
            for (int mi = 0; mi < 2; ++mi)
#pragma unroll
                for (int ni = 0; ni < 8; ++ni)
                    mma8(acc[mi][ni], a[mi], bf[ni][0], bf[ni][1]);
        }
    }

    // epilogue
    const int rB = blockIdx.y * 128 + wm * 32 + (l >> 2);
    const int cB = blockIdx.x * 128 + wn * 64 + (l & 3) * 2;
#pragma unroll
    for (int ni = 0; ni < 8; ++ni) {
        const int c = cB + ni * 8;
        float b0 = 0.f, b1 = 0.f;
        if (bias) { b0 = bias[c]; b1 = bias[c + 1]; }
#pragma unroll
        for (int mi = 0; mi < 2; ++mi) {
            *(float2*)(C + (size_t)(rB + mi*16    ) * N + c) =
                make_float2(acc[mi][ni][0] + b0, acc[mi][ni][1] + b1);
            *(float2*)(C + (size_t)(rB + mi*16 + 8) * N + c) =
                make_float2(acc[mi][ni][2] + b0, acc[mi][ni][3] + b1);
        }
    }
}

// ---------------- RoPE + split (Q pre-scaled; tf32-rounded) -----------------
__global__ void __launch_bounds__(256)
rope_split_kernel(const float* __restrict__ qkv,
                  const float* __restrict__ cosb, const float* __restrict__ sinb,
                  float* __restrict__ Q, float* __restrict__ K)
{
    size_t idx = (size_t)blockIdx.x * 256 + threadIdx.x;
    int d2 = (int)(idx & 63);
    size_t r = idx >> 6;
    int nh = (int)(r & 15); r >>= 4;
    int t  = (int)(r & 2047);
    int b  = (int)(r >> 11);

    const float* base = qkv + ((size_t)(b * T_ + t)) * 3 * HID_ + nh * HD_ + 2 * d2;
    float2 qp = *(const float2*)(base);
    float2 kp = *(const float2*)(base + HID_);
    float c = cosb[t * 64 + d2], s = sinb[t * 64 + d2];
    const float scale = 0.088388347648318447f;  // 1/sqrt(128)

    size_t o = (((size_t)(b * NH_ + nh)) * T_ + t) * HD_ + 2 * d2;
    *(float2*)(Q + o) = make_float2(f2tf((qp.x*c - qp.y*s) * scale),
                                    f2tf((qp.x*s + qp.y*c) * scale));
    *(float2*)(K + o) = make_float2(f2tf(kp.x*c - kp.y*s),
                                    f2tf(kp.x*s + kp.y*c));
}

// ---------------- V transpose: qkv v-slice -> [B,NH,HD,T] (tf32) ------------
__global__ void __launch_bounds__(256)
vtrans_kernel(const float* __restrict__ qkv, float* __restrict__ Vt)
{
    __shared__ float tile[32][33];
    const int t0 = blockIdx.x * 32, d0 = blockIdx.y * 32, bh = blockIdx.z;
    const int b = bh >> 4, h = bh & 15;
    const int tx = threadIdx.x & 31, ty = threadIdx.x >> 5;   // ty 0..7
#pragma unroll
    for (int p = 0; p < 4; ++p) {
        int tt = ty + p * 8;
        tile[tt][tx] = qkv[((size_t)(b * T_ + t0 + tt) * 3 + 2) * HID_ + h * HD_ + d0 + tx];
    }
    __syncthreads();
#pragma unroll
    for (int p = 0; p < 4; ++p) {
        int dd = ty + p * 8;
        Vt[((size_t)bh * HD_ + d0 + dd) * T_ + t0 + tx] = f2tf(tile[tx][dd]);
    }
}

// ---------------- Flash attention, tf32 mma ---------------------------------
// BM=128 (8 warps x 16 rows), BN=64 keys/iter, HD=128.
// smem: Qs[128][132], Ks[2][64][132], Vt[128][68], Ps[128][68]  = 200 KB
__global__ void __launch_bounds__(256, 1)
flash_tf32_kernel(const float* __restrict__ Q, const float* __restrict__ K,
                  const float* __restrict__ V, float* __restrict__ O)
{
    extern __shared__ __align__(16) float sm[];
    float* Qs = sm;                       // 128*132
    float* Ks = Qs + 128 * 132;           // 2*64*132
    float* Vt = Ks + 2 * 64 * 132;        // 128*68
    float* Ps = Vt + 128 * 68;            // 128*68

    const int tid = threadIdx.x, l = tid & 31, w = tid >> 5;
    const int bm = blockIdx.x, h = blockIdx.y, b = blockIdx.z;
    const float* Qg = Q + (((size_t)b * NH_ + h) * T_ + (size_t)bm * 128) * HD_;
    const float* Kg = K + ((size_t)b * NH_ + h) * T_ * HD_;
    const float* Vg = V + ((size_t)b * NH_ + h) * (size_t)HD_ * T_;
    const uint32_t sQ = smem_u32(Qs), sK = smem_u32(Ks), sV = smem_u32(Vt), sP = smem_u32(Ps);

    // prologue: Q (128x128) + K tile 0 (64x128) as one cp.async group
#pragma unroll
    for (int p = 0; p < 16; ++p) {
        int ci = tid + p * 256, r = ci >> 5, c = (ci & 31) * 4;
        cp16(sQ + (r * 132 + c) * 4, Qg + (size_t)r * HD_ + c);
    }
#pragma unroll
    for (int p = 0; p < 8; ++p) {
        int ci = tid + p * 256, r = ci >> 5, c = (ci & 31) * 4;
        cp16(sK + (r * 132 + c) * 4, Kg + (size_t)r * HD_ + c);
    }
    cp_commit();

    float o[16][4];
#pragma unroll
    for (int i = 0; i < 16; ++i)
#pragma unroll
        for (int j = 0; j < 4; ++j) o[i][j] = 0.f;
    float mA = -1e30f, mB = -1e30f, lA = 0.f, lB = 0.f;

    const int aOff  = (w*16 + (l & 7) + ((l >> 3) & 1) * 8) * 132 + ((l >> 3) >> 1) * 4;
    const int bOffK = ((l & 7) + ((l >> 4) & 1) * 8) * 132 + ((l >> 3) & 1) * 4;
    const int pOff  = (w*16 + (l & 7) + ((l >> 3) & 1) * 8) * 68 + ((l >> 3) >> 1) * 4;
    const int vOff  = ((l & 7) + ((l >> 4) & 1) * 8) * 68 + ((l >> 3) & 1) * 4;

    const int NIT = T_ / 64;
    for (int it = 0; it < NIT; ++it) {
        __syncthreads();                       // Vt/Ps free (prior PV done everywhere)
        // V(it) -> Vt
#pragma unroll
        for (int p = 0; p < 8; ++p) {
            int ci = tid + p * 256, r = ci >> 4, c = (ci & 15) * 4;
            cp16(sV + (r * 68 + c) * 4, Vg + (size_t)r * T_ + (size_t)it * 64 + c);
        }
        cp_commit();
        cp_wait<1>();                          // K(it) (and Q) ready; V(it) in flight
        __syncthreads();

        // prefetch K(it+1)
        if (it + 1 < NIT) {
            const float* Kn = Kg + (size_t)(it + 1) * 64 * HD_;
            const int o2 = ((it + 1) & 1) * 64 * 132;
#pragma unroll
            for (int p = 0; p < 8; ++p) {
                int ci = tid + p * 256, r = ci >> 5, c = (ci & 31) * 4;
                cp16(sK + (o2 + r * 132 + c) * 4, Kn + (size_t)r * HD_ + c);
            }
            cp_commit();
        }

        // ---- S = Q @ K^T ----
        const uint32_t kB = sK + (it & 1) * 64 * 132 * 4;
        float s[8][4];
#pragma unroll
        for (int i = 0; i < 8; ++i)
#pragma unroll
            for (int j = 0; j < 4; ++j) s[i][j] = 0.f;
#pragma unroll
        for (int ks = 0; ks < 16; ++ks) {
            const int k8 = ks * 8;
            uint32_t a[4];
            ldsm4(a, sQ + (aOff + k8) * 4);
#pragma unroll
            for (int j = 0; j < 4; ++j) {
                uint32_t t[4];
                ldsm4(t, kB + (bOffK + j * 16 * 132 + k8) * 4);
                mma8(s[2*j],   a, t[0], t[1]);
                mma8(s[2*j+1], a, t[2], t[3]);
            }
        }

        // ---- online softmax (rows A: c0,c1 ; rows B: c2,c3) ----
        float mxA = -1e30f, mxB = -1e30f;
#pragma unroll
        for (int j = 0; j < 8; ++j) {
            mxA = fmaxf(mxA, fmaxf(s[j][0], s[j][1]));
            mxB = fmaxf(mxB, fmaxf(s[j][2], s[j][3]));
        }
        mxA = fmaxf(mxA, __shfl_xor_sync(0xffffffffu, mxA, 1));
        mxA = fmaxf(mxA, __shfl_xor_sync(0xffffffffu, mxA, 2));
        mxB = fmaxf(mxB, __shfl_xor_sync(0xffffffffu, mxB, 1));
        mxB = fmaxf(mxB, __shfl_xor_sync(0xffffffffu, mxB, 2));
        const float mnA = fmaxf(mA, mxA), mnB = fmaxf(mB, mxB);
        const float cA = __expf(mA - mnA), cB = __expf(mB - mnB);
        mA = mnA; mB = mnB;
        float sA_ = 0.f, sB_ = 0.f;
#pragma unroll
        for (int j = 0; j < 8; ++j) {
            s[j][0] = __expf(s[j][0] - mnA);
            s[j][1] = __expf(s[j][1] - mnA);
            s[j][2] = __expf(s[j][2] - mnB);
            s[j][3] = __expf(s[j][3] - mnB);
            sA_ += s[j][0] + s[j][1];
            sB_ += s[j][2] + s[j][3];
        }
        sA_ += __shfl_xor_sync(0xffffffffu, sA_, 1);
        sA_ += __shfl_xor_sync(0xffffffffu, sA_, 2);
        sB_ += __shfl_xor_sync(0xffffffffu, sB_, 1);
        sB_ += __shfl_xor_sync(0xffffffffu, sB_, 2);
        lA = lA * cA + sA_;
        lB = lB * cB + sB_;
#pragma unroll
        for (int t = 0; t < 16; ++t) {
            o[t][0] *= cA; o[t][1] *= cA; o[t][2] *= cB; o[t][3] *= cB;
        }

        // ---- store P (own rows only) ----
        {
            const int pr = w * 16 + (l >> 2);
            float* P0 = Ps + pr * 68 + (l & 3) * 2;
            float* P1 = Ps + (pr + 8) * 68 + (l & 3) * 2;
#pragma unroll
            for (int j = 0; j < 8; ++j) {
                *(float2*)(P0 + j * 8) = make_float2(s[j][0], s[j][1]);
                *(float2*)(P1 + j * 8) = make_float2(s[j][2], s[j][3]);
            }
        }
        __syncwarp();
        if (it + 1 < NIT) cp_wait<1>(); else cp_wait<0>();   // V(it) done
        __syncthreads();

        // ---- O += P @ V ----
#pragma unroll
        for (int kv = 0; kv < 8; ++kv) {
            uint32_t a[4];
            ldsm4(a, sP + (pOff + kv * 8) * 4);
#pragma unroll
            for (int j = 0; j < 8; ++j) {
                uint32_t t[4];
                ldsm4(t, sV + (vOff + j * 16 * 68 + kv * 8) * 4);
                mma8(o[2*j],   a, t[0], t[1]);
                mma8(o[2*j+1], a, t[2], t[3]);
            }
        }
    }

    // ---- epilogue ----
    const float iA = 1.f / lA, iB = 1.f / lB;
    const int row = bm * 128 + w * 16 + (l >> 2);
    float* O0 = O + ((size_t)b * T_ + row) * HID_ + h * HD_ + (l & 3) * 2;
    float* O1 = O + ((size_t)b * T_ + row + 8) * HID_ + h * HD_ + (l & 3) * 2;
#pragma unroll
    for (int j = 0; j < 16; ++j) {
        *(float2*)(O0 + j * 8) = make_float2(o[j][0] * iA, o[j][1] * iA);
        *(float2*)(O1 + j * 8) = make_float2(o[j][2] * iB, o[j][3] * iB);
    }
}

// ---------------- launch ----------------------------------------------------
extern "C" void kernel_launch(void* const* d_in, const int* in_sizes, int n_in,
                              void* d_out, int out_size)
{
    const float* x      = (const float*)d_in[0];
    const float* w_qkv  = (const float*)d_in[1];
    const float* w_proj = (const float*)d_in[2];
    const float* b_proj = (const float*)d_in[3];
    const float* cosb   = (const float*)d_in[4];
    const float* sinb   = (const float*)d_in[5];
    float* out = (float*)d_out;

    float *qkv, *q, *k, *v, *attn;
    cudaGetSymbolAddress((void**)&qkv,  g_qkv);
    cudaGetSymbolAddress((void**)&q,    g_q);
    cudaGetSymbolAddress((void**)&k,    g_k);
    cudaGetSymbolAddress((void**)&v,    g_v);
    cudaGetSymbolAddress((void**)&attn, g_attn);

    const int SMEM_GEMM = 4 * 128 * GS * 4;                                   // 73728
    const int SMEM_ATT  = (128*132 + 2*64*132 + 128*68 + 128*68) * 4;         // 204800
    cudaFuncSetAttribute(gemm_tf32_nt,
                         cudaFuncAttributeMaxDynamicSharedMemorySize, SMEM_GEMM);
    cudaFuncSetAttribute(flash_tf32_kernel,
                         cudaFuncAttributeMaxDynamicSharedMemorySize, SMEM_ATT);

    const int M = B_ * T_;   // 8192

    // 1) QKV projection
    dim3 g1(3 * HID_ / 128, M / 128);
    gemm_tf32_nt<<<g1, 256, SMEM_GEMM>>>(x, w_qkv, nullptr, qkv, M, 3 * HID_, HID_);

    // 2) RoPE + split (Q scaled+tf32, K tf32)
    size_t total = (size_t)B_ * T_ * NH_ * 64;
    rope_split_kernel<<<(unsigned)(total / 256), 256>>>(qkv, cosb, sinb, q, k);

    // 3) V transpose -> [B,NH,HD,T] (tf32)
    dim3 gv(T_ / 32, HD_ / 32, B_ * NH_);
    vtrans_kernel<<<gv, 256>>>(qkv, v);

    // 4) Flash attention (tf32 mma)
    dim3 ga(T_ / 128, NH_, B_);
    flash_tf32_kernel<<<ga, 256, SMEM_ATT>>>(q, k, v, attn);

    // 5) Output projection + bias
    dim3 g2(HID_ / 128, M / 128);
    gemm_tf32_nt<<<g2, 256, SMEM_GEMM>>>(attn, w_proj, b_proj, out, M, HID_, HID_);
}

// round 4
// speedup vs baseline: 7.2453x; 1.0440x over previous
#include <cuda_runtime.h>
#include <math.h>
#include <stdint.h>

#define B_   4
#define T_   2048
#define HID_ 2048
#define NH_  16
#define HD_  128

// ---------------- scratch ---------------------------------------------------
__device__ __align__(128) float g_qkv [(size_t)B_ * T_ * 3 * HID_];   // [B,T,3,HID]
__device__ __align__(128) float g_q   [(size_t)B_ * NH_ * T_ * HD_];  // [B,NH,T,HD] tf32, scaled by 1/sqrt(HD)*log2e
__device__ __align__(128) float g_k   [(size_t)B_ * NH_ * T_ * HD_];  // [B,NH,T,HD] tf32
__device__ __align__(128) float g_v   [(size_t)B_ * NH_ * T_ * HD_];  // [B,NH,HD,T] tf32 (transposed)
__device__ __align__(128) float g_attn[(size_t)B_ * T_ * HID_];       // [B,T,HID]  tf32-rounded
__device__ __align__(128) float g_xtf [(size_t)B_ * T_ * HID_];       // x, tf32-rounded
__device__ __align__(128) float g_wqkv[(size_t)3 * HID_ * HID_];      // w_qkv, tf32-rounded
__device__ __align__(128) float g_wprj[(size_t)HID_ * HID_];          // w_proj, tf32-rounded

// ---------------- PTX helpers ----------------------------------------------
__device__ __forceinline__ uint32_t smem_u32(const void* p) {
    return (uint32_t)__cvta_generic_to_shared(p);
}
__device__ __forceinline__ void cp16(uint32_t s, const void* g) {
    asm volatile("cp.async.cg.shared.global [%0],[%1],16;\n" :: "r"(s), "l"(g));
}
__device__ __forceinline__ void cp_commit() { asm volatile("cp.async.commit_group;\n"); }
template<int N> __device__ __forceinline__ void cp_wait() {
    asm volatile("cp.async.wait_group %0;\n" :: "n"(N));
}
__device__ __forceinline__ void ldsm4(uint32_t* r, uint32_t a) {
    asm volatile("ldmatrix.sync.aligned.m8n8.x4.shared.b16 {%0,%1,%2,%3},[%4];\n"
                 : "=r"(r[0]), "=r"(r[1]), "=r"(r[2]), "=r"(r[3]) : "r"(a));
}
__device__ __forceinline__ void mma8(float* c, const uint32_t* a, uint32_t b0, uint32_t b1) {
    asm volatile("mma.sync.aligned.m16n8k8.row.col.f32.tf32.tf32.f32 "
                 "{%0,%1,%2,%3},{%4,%5,%6,%7},{%8,%9},{%0,%1,%2,%3};\n"
                 : "+f"(c[0]), "+f"(c[1]), "+f"(c[2]), "+f"(c[3])
                 : "r"(a[0]), "r"(a[1]), "r"(a[2]), "r"(a[3]), "r"(b0), "r"(b1));
}
__device__ __forceinline__ uint32_t f2tfu(float x) {
    uint32_t r; asm("cvt.rna.tf32.f32 %0,%1;\n" : "=r"(r) : "f"(x)); return r;
}
__device__ __forceinline__ float f2tf(float x) { return __uint_as_float(f2tfu(x)); }

// ---------------- tf32 GEMM v2 (NT): C[M,N]=A[M,K]@B[N,K]^T (+bias) ---------
// Tile 128x256, 512 threads (16 warps: 4M x 4N), warp tile 32x64, BK=32,
// cp.async double buffer. Operands MUST be pre-rounded to tf32 (no in-loop cvt).
#define GS 36   // smem row stride (floats)

__global__ void __launch_bounds__(512, 1)
gemm_tf32_nt(const float* __restrict__ A, const float* __restrict__ Bw,
             const float* __restrict__ bias, float* __restrict__ C,
             int M, int N, int K)
{
    extern __shared__ __align__(16) float gsm[];
    float* As = gsm;               // [2][128*GS]
    float* Bs = gsm + 2*128*GS;    // [2][256*GS]

    const int tid = threadIdx.x, l = tid & 31, w = tid >> 5;
    const int wm = w & 3, wn = w >> 2;           // 4 x 4 warp grid
    const float* Ag = A  + (size_t)blockIdx.y * 128 * K;
    const float* Bg = Bw + (size_t)blockIdx.x * 256 * K;
    const uint32_t sA = smem_u32(As), sB = smem_u32(Bs);

    float acc[2][8][4];
#pragma unroll
    for (int i = 0; i < 2; ++i)
#pragma unroll
        for (int j = 0; j < 8; ++j)
#pragma unroll
            for (int k = 0; k < 4; ++k) acc[i][j][k] = 0.f;

    const int aOff = (wm*32 + (l & 7) + ((l >> 3) & 1) * 8) * GS + ((l >> 3) >> 1) * 4;
    const int bOff = (wn*64 + (l & 7) + ((l >> 4) & 1) * 8) * GS + ((l >> 3) & 1) * 4;

    // loaders: A 128x32 (1024 cp16 -> 2/thread), B 256x32 (2048 cp16 -> 4/thread)
    const int lrA = tid >> 3, lcA = (tid & 7) * 4;      // A rows 0..63 (x2)
    auto load = [&](int kt, int buf) {
        const float* Ak = Ag + (size_t)kt * 32;
        const float* Bk = Bg + (size_t)kt * 32;
        const int oA = buf * 128 * GS, oB = buf * 256 * GS;
#pragma unroll
        for (int p = 0; p < 2; ++p) {
            int r = lrA + p * 64;
            cp16(sA + (oA + r*GS + lcA) * 4, Ak + (size_t)r * K + lcA);
        }
#pragma unroll
        for (int p = 0; p < 4; ++p) {
            int r = lrA + p * 64;
            cp16(sB + (oB + r*GS + lcA) * 4, Bk + (size_t)r * K + lcA);
        }
        cp_commit();
    };

    load(0, 0);

    const int nkt = K >> 5;
    for (int kt = 0; kt < nkt; ++kt) {
        const int buf = kt & 1;
        cp_wait<0>();
        __syncthreads();
        if (kt + 1 < nkt) load(kt + 1, buf ^ 1);

        const uint32_t aB = sA + buf * 128 * GS * 4;
        const uint32_t bB = sB + buf * 256 * GS * 4;
#pragma unroll
        for (int ks = 0; ks < 4; ++ks) {
            const int k8 = ks * 8;
            uint32_t a[2][4], bf[8][2];
#pragma unroll
            for (int mi = 0; mi < 2; ++mi)
                ldsm4(a[mi], aB + (aOff + mi*16*GS + k8) * 4);
#pragma unroll
            for (int j = 0; j < 4; ++j) {
                uint32_t t[4];
                ldsm4(t, bB + (bOff + j*16*GS + k8) * 4);
                bf[2*j][0] = t[0]; bf[2*j][1] = t[1];
                bf[2*j+1][0] = t[2]; bf[2*j+1][1] = t[3];
            }
#pragma unroll
            for (int mi = 0; mi < 2; ++mi)
#pragma unroll
                for (int ni = 0; ni < 8; ++ni)
                    mma8(acc[mi][ni], a[mi], bf[ni][0], bf[ni][1]);
        }
        __syncthreads();
    }

    // epilogue
    const int rB = blockIdx.y * 128 + wm * 32 + (l >> 2);
    const int cB = blockIdx.x * 256 + wn * 64 + (l & 3) * 2;
#pragma unroll
    for (int ni = 0; ni < 8; ++ni) {
        const int c = cB + ni * 8;
        float b0 = 0.f, b1 = 0.f;
        if (bias) { b0 = bias[c]; b1 = bias[c + 1]; }
#pragma unroll
        for (int mi = 0; mi < 2; ++mi) {
            *(float2*)(C + (size_t)(rB + mi*16    ) * N + c) =
                make_float2(acc[mi][ni][0] + b0, acc[mi][ni][1] + b1);
            *(float2*)(C + (size_t)(rB + mi*16 + 8) * N + c) =
                make_float2(acc[mi][ni][2] + b0, acc[mi][ni][3] + b1);
        }
    }
}

// ---------------- tf32-RNA rounding pass ------------------------------------
__global__ void __launch_bounds__(256)
cvt_tf32_kernel(const float* __restrict__ in, float* __restrict__ out)
{
    size_t i = ((size_t)blockIdx.x * 256 + threadIdx.x) * 4;
    float4 v = *(const float4*)(in + i);
    v.x = f2tf(v.x); v.y = f2tf(v.y); v.z = f2tf(v.z); v.w = f2tf(v.w);
    *(float4*)(out + i) = v;
}

// ---------------- RoPE + split (Q pre-scaled by 1/sqrt(HD)*log2e) -----------
__global__ void __launch_bounds__(256)
rope_split_kernel(const float* __restrict__ qkv,
                  const float* __restrict__ cosb, const float* __restrict__ sinb,
                  float* __restrict__ Q, float* __restrict__ K)
{
    size_t idx = (size_t)blockIdx.x * 256 + threadIdx.x;
    int d2 = (int)(idx & 63);
    size_t r = idx >> 6;
    int nh = (int)(r & 15); r >>= 4;
    int t  = (int)(r & 2047);
    int b  = (int)(r >> 11);

    const float* base = qkv + ((size_t)(b * T_ + t)) * 3 * HID_ + nh * HD_ + 2 * d2;
    float2 qp = *(const float2*)(base);
    float2 kp = *(const float2*)(base + HID_);
    float c = cosb[t * 64 + d2], s = sinb[t * 64 + d2];
    const float scale = 0.088388347648318447f * 1.4426950408889634f; // 1/sqrt(128)*log2(e)

    size_t o = (((size_t)(b * NH_ + nh)) * T_ + t) * HD_ + 2 * d2;
    *(float2*)(Q + o) = make_float2(f2tf((qp.x*c - qp.y*s) * scale),
                                    f2tf((qp.x*s + qp.y*c) * scale));
    *(float2*)(K + o) = make_float2(f2tf(kp.x*c - kp.y*s),
                                    f2tf(kp.x*s + kp.y*c));
}

// ---------------- V transpose: qkv v-slice -> [B,NH,HD,T] (tf32) ------------
__global__ void __launch_bounds__(256)
vtrans_kernel(const float* __restrict__ qkv, float* __restrict__ Vt)
{
    __shared__ float tile[32][33];
    const int t0 = blockIdx.x * 32, d0 = blockIdx.y * 32, bh = blockIdx.z;
    const int b = bh >> 4, h = bh & 15;
    const int tx = threadIdx.x & 31, ty = threadIdx.x >> 5;
#pragma unroll
    for (int p = 0; p < 4; ++p) {
        int tt = ty + p * 8;
        tile[tt][tx] = qkv[((size_t)(b * T_ + t0 + tt) * 3 + 2) * HID_ + h * HD_ + d0 + tx];
    }
    __syncthreads();
#pragma unroll
    for (int p = 0; p < 4; ++p) {
        int dd = ty + p * 8;
        Vt[((size_t)bh * HD_ + d0 + dd) * T_ + t0 + tx] = f2tf(tile[tx][dd]);
    }
}

// ---------------- Flash attention, tf32 mma.sync ----------------------------
__global__ void __launch_bounds__(256, 1)
flash_tf32_kernel(const float* __restrict__ Q, const float* __restrict__ K,
                  const float* __restrict__ V, float* __restrict__ O)
{
    extern __shared__ __align__(16) float sm[];
    float* Qs = sm;                       // 128*132
    float* Ks = Qs + 128 * 132;           // 2*64*132
    float* Vt = Ks + 2 * 64 * 132;        // 128*68
    float* Ps = Vt + 128 * 68;            // 128*68

    const int tid = threadIdx.x, l = tid & 31, w = tid >> 5;
    const int bm = blockIdx.x, h = blockIdx.y, b = blockIdx.z;
    const float* Qg = Q + (((size_t)b * NH_ + h) * T_ + (size_t)bm * 128) * HD_;
    const float* Kg = K + ((size_t)b * NH_ + h) * T_ * HD_;
    const float* Vg = V + ((size_t)b * NH_ + h) * (size_t)HD_ * T_;
    const uint32_t sQ = smem_u32(Qs), sK = smem_u32(Ks), sV = smem_u32(Vt), sP = smem_u32(Ps);

#pragma unroll
    for (int p = 0; p < 16; ++p) {
        int ci = tid + p * 256, r = ci >> 5, c = (ci & 31) * 4;
        cp16(sQ + (r * 132 + c) * 4, Qg + (size_t)r * HD_ + c);
    }
#pragma unroll
    for (int p = 0; p < 8; ++p) {
        int ci = tid + p * 256, r = ci >> 5, c = (ci & 31) * 4;
        cp16(sK + (r * 132 + c) * 4, Kg + (size_t)r * HD_ + c);
    }
    cp_commit();

    float o[16][4];
#pragma unroll
    for (int i = 0; i < 16; ++i)
#pragma unroll
        for (int j = 0; j < 4; ++j) o[i][j] = 0.f;
    float mA = -1e30f, mB = -1e30f, lA = 0.f, lB = 0.f;

    const int aOff  = (w*16 + (l & 7) + ((l >> 3) & 1) * 8) * 132 + ((l >> 3) >> 1) * 4;
    const int bOffK = ((l & 7) + ((l >> 4) & 1) * 8) * 132 + ((l >> 3) & 1) * 4;
    const int pOff  = (w*16 + (l & 7) + ((l >> 3) & 1) * 8) * 68 + ((l >> 3) >> 1) * 4;
    const int vOff  = ((l & 7) + ((l >> 4) & 1) * 8) * 68 + ((l >> 3) & 1) * 4;

    const int NIT = T_ / 64;
    for (int it = 0; it < NIT; ++it) {
        __syncthreads();
#pragma unroll
        for (int p = 0; p < 8; ++p) {
            int ci = tid + p * 256, r = ci >> 4, c = (ci & 15) * 4;
            cp16(sV + (r * 68 + c) * 4, Vg + (size_t)r * T_ + (size_t)it * 64 + c);
        }
        cp_commit();
        cp_wait<1>();
        __syncthreads();

        if (it + 1 < NIT) {
            const float* Kn = Kg + (size_t)(it + 1) * 64 * HD_;
            const int o2 = ((it + 1) & 1) * 64 * 132;
#pragma unroll
            for (int p = 0; p < 8; ++p) {
                int ci = tid + p * 256, r = ci >> 5, c = (ci & 31) * 4;
                cp16(sK + (o2 + r * 132 + c) * 4, Kn + (size_t)r * HD_ + c);
            }
            cp_commit();
        }

        const uint32_t kB = sK + (it & 1) * 64 * 132 * 4;
        float s[8][4];
#pragma unroll
        for (int i = 0; i < 8; ++i)
#pragma unroll
            for (int j = 0; j < 4; ++j) s[i][j] = 0.f;
#pragma unroll
        for (int ks = 0; ks < 16; ++ks) {
            const int k8 = ks * 8;
            uint32_t a[4];
            ldsm4(a, sQ + (aOff + k8) * 4);
#pragma unroll
            for (int j = 0; j < 4; ++j) {
                uint32_t t[4];
                ldsm4(t, kB + (bOffK + j * 16 * 132 + k8) * 4);
                mma8(s[2*j],   a, t[0], t[1]);
                mma8(s[2*j+1], a, t[2], t[3]);
            }
        }

        float mxA = -1e30f, mxB = -1e30f;
#pragma unroll
        for (int j = 0; j < 8; ++j) {
            mxA = fmaxf(mxA, fmaxf(s[j][0], s[j][1]));
            mxB = fmaxf(mxB, fmaxf(s[j][2], s[j][3]));
        }
        mxA = fmaxf(mxA, __shfl_xor_sync(0xffffffffu, mxA, 1));
        mxA = fmaxf(mxA, __shfl_xor_sync(0xffffffffu, mxA, 2));
        mxB = fmaxf(mxB, __shfl_xor_sync(0xffffffffu, mxB, 1));
        mxB = fmaxf(mxB, __shfl_xor_sync(0xffffffffu, mxB, 2));
        const float mnA = fmaxf(mA, mxA), mnB = fmaxf(mB, mxB);
        const float cA = exp2f(mA - mnA), cB = exp2f(mB - mnB);
        mA = mnA; mB = mnB;
        float sA_ = 0.f, sB_ = 0.f;
#pragma unroll
        for (int j = 0; j < 8; ++j) {
            s[j][0] = exp2f(s[j][0] - mnA);
            s[j][1] = exp2f(s[j][1] - mnA);
            s[j][2] = exp2f(s[j][2] - mnB);
            s[j][3] = exp2f(s[j][3] - mnB);
            sA_ += s[j][0] + s[j][1];
            sB_ += s[j][2] + s[j][3];
        }
        sA_ += __shfl_xor_sync(0xffffffffu, sA_, 1);
        sA_ += __shfl_xor_sync(0xffffffffu, sA_, 2);
        sB_ += __shfl_xor_sync(0xffffffffu, sB_, 1);
        sB_ += __shfl_xor_sync(0xffffffffu, sB_, 2);
        lA = lA * cA + sA_;
        lB = lB * cB + sB_;
#pragma unroll
        for (int t = 0; t < 16; ++t) {
            o[t][0] *= cA; o[t][1] *= cA; o[t][2] *= cB; o[t][3] *= cB;
        }

        {
            const int pr = w * 16 + (l >> 2);
            float* P0 = Ps + pr * 68 + (l & 3) * 2;
            float* P1 = Ps + (pr + 8) * 68 + (l & 3) * 2;
#pragma unroll
            for (int j = 0; j < 8; ++j) {
                *(float2*)(P0 + j * 8) = make_float2(s[j][0], s[j][1]);
                *(float2*)(P1 + j * 8) = make_float2(s[j][2], s[j][3]);
            }
        }
        __syncwarp();
        if (it + 1 < NIT) cp_wait<1>(); else cp_wait<0>();
        __syncthreads();

#pragma unroll
        for (int kv = 0; kv < 8; ++kv) {
            uint32_t a[4];
            ldsm4(a, sP + (pOff + kv * 8) * 4);
#pragma unroll
            for (int j = 0; j < 8; ++j) {
                uint32_t t[4];
                ldsm4(t, sV + (vOff + j * 16 * 68 + kv * 8) * 4);
                mma8(o[2*j],   a, t[0], t[1]);
                mma8(o[2*j+1], a, t[2], t[3]);
            }
        }
    }

    const float iA = 1.f / lA, iB = 1.f / lB;
    const int row = bm * 128 + w * 16 + (l >> 2);
    float* O0 = O + ((size_t)b * T_ + row) * HID_ + h * HD_ + (l & 3) * 2;
    float* O1 = O + ((size_t)b * T_ + row + 8) * HID_ + h * HD_ + (l & 3) * 2;
#pragma unroll
    for (int j = 0; j < 16; ++j) {
        *(float2*)(O0 + j * 8) = make_float2(f2tf(o[j][0] * iA), f2tf(o[j][1] * iA));
        *(float2*)(O1 + j * 8) = make_float2(f2tf(o[j][2] * iB), f2tf(o[j][3] * iB));
    }
}

// ---------------- launch ----------------------------------------------------
extern "C" void kernel_launch(void* const* d_in, const int* in_sizes, int n_in,
                              void* d_out, int out_size)
{
    const float* x      = (const float*)d_in[0];
    const float* w_qkv  = (const float*)d_in[1];
    const float* w_proj = (const float*)d_in[2];
    const float* b_proj = (const float*)d_in[3];
    const float* cosb   = (const float*)d_in[4];
    const float* sinb   = (const float*)d_in[5];
    float* out = (float*)d_out;

    float *qkv, *q, *k, *v, *attn, *xtf, *wqkv, *wprj;
    cudaGetSymbolAddress((void**)&qkv,  g_qkv);
    cudaGetSymbolAddress((void**)&q,    g_q);
    cudaGetSymbolAddress((void**)&k,    g_k);
    cudaGetSymbolAddress((void**)&v,    g_v);
    cudaGetSymbolAddress((void**)&attn, g_attn);
    cudaGetSymbolAddress((void**)&xtf,  g_xtf);
    cudaGetSymbolAddress((void**)&wqkv, g_wqkv);
    cudaGetSymbolAddress((void**)&wprj, g_wprj);

    const int SMEM_GEMM = (2*128*GS + 2*256*GS) * 4;                   // 110592
    const int SMEM_ATT  = (128*132 + 2*64*132 + 128*68 + 128*68) * 4;  // 204800
    cudaFuncSetAttribute(gemm_tf32_nt,
                         cudaFuncAttributeMaxDynamicSharedMemorySize, SMEM_GEMM);
    cudaFuncSetAttribute(flash_tf32_kernel,
                         cudaFuncAttributeMaxDynamicSharedMemorySize, SMEM_ATT);

    const int M = B_ * T_;   // 8192

    // 0) tf32-RNA rounding of GEMM operands
    cvt_tf32_kernel<<<(unsigned)((size_t)M * HID_ / 1024), 256>>>(x, xtf);
    cvt_tf32_kernel<<<(unsigned)((size_t)3 * HID_ * HID_ / 1024), 256>>>(w_qkv, wqkv);
    cvt_tf32_kernel<<<(unsigned)((size_t)HID_ * HID_ / 1024), 256>>>(w_proj, wprj);

    // 1) QKV projection: [8192,2048] @ [6144,2048]^T
    dim3 g1(3 * HID_ / 256, M / 128);
    gemm_tf32_nt<<<g1, 512, SMEM_GEMM>>>(xtf, wqkv, nullptr, qkv, M, 3 * HID_, HID_);

    // 2) RoPE + split
    size_t total = (size_t)B_ * T_ * NH_ * 64;
    rope_split_kernel<<<(unsigned)(total / 256), 256>>>(qkv, cosb, sinb, q, k);

    // 3) V transpose -> [B,NH,HD,T]
    dim3 gv(T_ / 32, HD_ / 32, B_ * NH_);
    vtrans_kernel<<<gv, 256>>>(qkv, v);

    // 4) Flash attention
    dim3 ga(T_ / 128, NH_, B_);
    flash_tf32_kernel<<<ga, 256, SMEM_ATT>>>(q, k, v, attn);

    // 5) Output projection + bias
    dim3 g2(HID_ / 256, M / 128);
    gemm_tf32_nt<<<g2, 512, SMEM_GEMM>>>(attn, wprj, b_proj, out, M, HID_, HID_);
}